// round 1
// baseline (speedup 1.0000x reference)
#include <cuda_runtime.h>

#define NP    200
#define NVERT 6890
#define NJ    24
#define MDIM  20670   // NVERT*3
#define RDIM  391     // 23*17
#define GBM   40
#define GBN   160

__constant__ int c_PARENT[NJ] = {0,0,0,0,1,2,3,4,5,6,7,8,9,9,9,12,13,14,16,17,18,19,20,21};
__constant__ int c_LEN[NJ]    = {4,3,3,3,3,3,3,3,3,2,2,2,4,3,3,2,3,3,3,3,3,3,2,2};
__constant__ int c_NBR[NJ][4] = {
  {0,1,2,3},{0,1,4,0},{0,2,5,0},{0,3,6,0},{1,4,7,0},{2,5,8,0},{3,6,9,0},{4,7,10,0},
  {5,8,11,0},{6,9,0,0},{7,10,0,0},{8,11,0,0},{12,13,14,15},{12,13,16,0},{12,14,17,0},{12,15,0,0},
  {13,16,18,0},{14,17,19,0},{16,18,20,0},{17,19,21,0},{18,20,22,0},{19,21,23,0},{20,22,0,0},{21,23,0,0}};

// Scratch (static device globals; no runtime allocation)
__device__ float g_QMT[RDIM*NP];     // qm transposed: [r][p]
__device__ float g_Gp [NP*NJ*12];    // per-pose 3x4 world transforms (with -R*J offset)
__device__ float g_WcT[NJ*NVERT];    // normalized weights, transposed [k][n]
__device__ float g_Kp [RDIM*MDIM];   // K' = relu(A) folded into K_mats
__device__ float g_Tp [NP*MDIM];     // T_p = QM @ K' + T
__device__ float g_acc[32];          // 0:E_D 1:E_Wi 2:E_W 3:E_A 4..26:E_K[j] (sum of squares)

__global__ void init_kernel() {
  if (threadIdx.x < 32) g_acc[threadIdx.x] = 0.f;
}

// ---------------- per-pose: quats, qm rows, kinematic chain ----------------
__global__ void pose_kernel(const float* __restrict__ theta,
                            const float* __restrict__ Jin,
                            const float* __restrict__ beta2) {
  int p = blockIdx.x*blockDim.x + threadIdx.x;
  if (p >= NP) return;
  const float* th = theta + p*72;
  const float* Jp = Jin + p*72;

  float q[NJ][4];
  float Rl[NJ][9];
  float tl[NJ][3];
  for (int k = 0; k < NJ; ++k) {
    float x = th[3*k], y = th[3*k+1], z = th[3*k+2];
    float s2 = x*x + y*y + z*z;
    // quaternion (angle clamp 1e-16 on s2, per reference _axis2quat)
    float aq = sqrtf(fmaxf(s2, 1e-16f));
    float sh = sinf(0.5f*aq);
    float iq = 1.f/aq;
    q[k][0] = x*iq*sh; q[k][1] = y*iq*sh; q[k][2] = z*iq*sh;
    q[k][3] = cosf(0.5f*aq) - 1.f;
    // rodrigues (angle clamp 1e-8 on norm, per reference _rodrigues)
    float a = fmaxf(sqrtf(s2), 1e-8f);
    float ia = 1.f/a;
    float nx = x*ia, ny = y*ia, nz = z*ia;
    float c = cosf(a), s = sinf(a), t1 = 1.f - c;
    Rl[k][0] = c + t1*nx*nx;    Rl[k][1] = t1*nx*ny - s*nz; Rl[k][2] = t1*nx*nz + s*ny;
    Rl[k][3] = t1*nx*ny + s*nz; Rl[k][4] = c + t1*ny*ny;    Rl[k][5] = t1*ny*nz - s*nx;
    Rl[k][6] = t1*nx*nz - s*ny; Rl[k][7] = t1*ny*nz + s*nx; Rl[k][8] = c + t1*nz*nz;
    if (k == 0) { tl[k][0]=Jp[0]; tl[k][1]=Jp[1]; tl[k][2]=Jp[2]; }
    else {
      int par = c_PARENT[k];
      tl[k][0] = Jp[3*k]   - Jp[3*par];
      tl[k][1] = Jp[3*k+1] - Jp[3*par+1];
      tl[k][2] = Jp[3*k+2] - Jp[3*par+2];
    }
  }
  // kinematic chain
  float Rw[NJ][9], tw[NJ][3];
  for (int i = 0; i < 9; ++i) Rw[0][i] = Rl[0][i];
  for (int i = 0; i < 3; ++i) tw[0][i] = tl[0][i];
  for (int k = 1; k < NJ; ++k) {
    int par = c_PARENT[k];
    for (int i = 0; i < 3; ++i) {
      for (int j = 0; j < 3; ++j) {
        Rw[k][i*3+j] = Rw[par][i*3+0]*Rl[k][0+j] + Rw[par][i*3+1]*Rl[k][3+j] + Rw[par][i*3+2]*Rl[k][6+j];
      }
      tw[k][i] = Rw[par][i*3+0]*tl[k][0] + Rw[par][i*3+1]*tl[k][1] + Rw[par][i*3+2]*tl[k][2] + tw[par][i];
    }
  }
  // G' = [Rw | tw - Rw*J]
  for (int k = 0; k < NJ; ++k) {
    float jx = Jp[3*k], jy = Jp[3*k+1], jz = Jp[3*k+2];
    for (int i = 0; i < 3; ++i) {
      float off = Rw[k][i*3]*jx + Rw[k][i*3+1]*jy + Rw[k][i*3+2]*jz;
      g_Gp[p*288 + k*12 + i*4 + 0] = Rw[k][i*3+0];
      g_Gp[p*288 + k*12 + i*4 + 1] = Rw[k][i*3+1];
      g_Gp[p*288 + k*12 + i*4 + 2] = Rw[k][i*3+2];
      g_Gp[p*288 + k*12 + i*4 + 3] = tw[k][i] - off;
    }
  }
  // qm rows (note: mask row j uses LEN[j], beta for joint j+1 uses LEN[j+1] — per reference)
  float b2 = beta2[0];
  for (int j = 0; j < 23; ++j) {
    int jj = j + 1;
    int limit = 4*c_LEN[j] + 1;
    int bpos  = 4*c_LEN[jj];
    for (int l = 0; l < 17; ++l) {
      float v = 0.f;
      if (l < 16) {
        int g = l >> 2, cc = l & 3;
        if (g < c_LEN[jj]) v = q[c_NBR[jj][g]][cc];
      }
      if (l == bpos) v += b2;
      if (l >= limit) v = 0.f;
      g_QMT[(j*17 + l)*NP + p] = v;   // transposed for coalesced GEMM loads
    }
  }
}

// ---------------- weights: W_change, E_Wi, E_W, E_A ----------------
__global__ void w_kernel(const float* __restrict__ Wp, const float* __restrict__ Wi,
                         const float* __restrict__ A) {
  __shared__ float sb0[8], sb1[8], sb2[8];
  int n = blockIdx.x*blockDim.x + threadIdx.x;
  float ewi = 0.f, ew = 0.f, ea = 0.f;
  if (n < NVERT) {
    float w[NJ]; float s = 0.f;
    #pragma unroll
    for (int k = 0; k < NJ; ++k) { w[k] = fmaxf(Wp[n*NJ+k], 0.f); s += w[k]; }
    float inv = 1.f/(s + 1e-8f);
    #pragma unroll
    for (int k = 0; k < NJ; ++k) {
      float wc = w[k]*inv;
      g_WcT[k*NVERT + n] = wc;
      float d = wc - Wi[n*NJ+k];
      ewi += d*d;
      ew  += fabsf(wc);
    }
    for (int j = 0; j < 23; ++j) ea += fabsf(A[j*NVERT + n]);
  }
  for (int o = 16; o > 0; o >>= 1) {
    ewi += __shfl_down_sync(0xffffffffu, ewi, o);
    ew  += __shfl_down_sync(0xffffffffu, ew,  o);
    ea  += __shfl_down_sync(0xffffffffu, ea,  o);
  }
  int lane = threadIdx.x & 31, wid = threadIdx.x >> 5;
  if (lane == 0) { sb0[wid]=ewi; sb1[wid]=ew; sb2[wid]=ea; }
  __syncthreads();
  if (wid == 0) {
    ewi = (lane < 8) ? sb0[lane] : 0.f;
    ew  = (lane < 8) ? sb1[lane] : 0.f;
    ea  = (lane < 8) ? sb2[lane] : 0.f;
    for (int o = 4; o > 0; o >>= 1) {
      ewi += __shfl_down_sync(0xffffffffu, ewi, o);
      ew  += __shfl_down_sync(0xffffffffu, ew,  o);
      ea  += __shfl_down_sync(0xffffffffu, ea,  o);
    }
    if (lane == 0) {
      atomicAdd(&g_acc[1], ewi);
      atomicAdd(&g_acc[2], ew);
      atomicAdd(&g_acc[3], ea);
    }
  }
}

// ---------------- K' = relu(A) ⊙ K, plus E_K sum-of-squares ----------------
__global__ void kprime_kernel(const float* __restrict__ A, const float* __restrict__ K) {
  __shared__ float sb[8];
  int r = blockIdx.x;            // 0..390
  int j = r / 17;
  const float* Krow = K + (size_t)r*MDIM;
  float* Kprow = g_Kp + (size_t)r*MDIM;
  const float* Aj = A + j*NVERT;
  float ss = 0.f;
  for (int m = threadIdx.x; m < MDIM; m += blockDim.x) {
    float kv = Krow[m];
    float a  = fmaxf(Aj[m/3], 0.f);
    Kprow[m] = a*kv;
    ss += kv*kv;
  }
  for (int o = 16; o > 0; o >>= 1) ss += __shfl_down_sync(0xffffffffu, ss, o);
  int lane = threadIdx.x & 31, wid = threadIdx.x >> 5;
  if (lane == 0) sb[wid] = ss;
  __syncthreads();
  if (wid == 0) {
    ss = (lane < 8) ? sb[lane] : 0.f;
    for (int o = 4; o > 0; o >>= 1) ss += __shfl_down_sync(0xffffffffu, ss, o);
    if (lane == 0) atomicAdd(&g_acc[4 + j], ss);
  }
}

// ---------------- GEMM: T_p = QM(200x391) @ K'(391x20670) + T ----------------
__global__ void gemm_kernel(const float* __restrict__ T) {
  __shared__ float As[17][GBM];
  __shared__ float Bs[17][GBN];
  int m0 = blockIdx.x*GBN;
  int p0 = blockIdx.y*GBM;
  int tid = threadIdx.x;
  int tx = tid & 31, ty = tid >> 5;   // 32 x 8
  float acc[5][5];
  #pragma unroll
  for (int i = 0; i < 5; ++i)
    #pragma unroll
    for (int jj = 0; jj < 5; ++jj) acc[i][jj] = 0.f;

  for (int jb = 0; jb < 23; ++jb) {
    for (int i = tid; i < 17*GBM; i += 256) {
      int l = i / GBM, pp = i - l*GBM;
      As[l][pp] = g_QMT[(jb*17 + l)*NP + p0 + pp];
    }
    for (int i = tid; i < 17*GBN; i += 256) {
      int l = i / GBN, mm = i - l*GBN;
      int m = m0 + mm;
      Bs[l][mm] = (m < MDIM) ? g_Kp[(size_t)(jb*17 + l)*MDIM + m] : 0.f;
    }
    __syncthreads();
    #pragma unroll
    for (int l = 0; l < 17; ++l) {
      float a[5], b[5];
      #pragma unroll
      for (int i = 0; i < 5; ++i)  a[i]  = As[l][ty + 8*i];
      #pragma unroll
      for (int jj = 0; jj < 5; ++jj) b[jj] = Bs[l][tx + 32*jj];
      #pragma unroll
      for (int i = 0; i < 5; ++i)
        #pragma unroll
        for (int jj = 0; jj < 5; ++jj) acc[i][jj] += a[i]*b[jj];
    }
    __syncthreads();
  }
  #pragma unroll
  for (int i = 0; i < 5; ++i) {
    int p = p0 + ty + 8*i;          // always < 200 (5 tiles x 40)
    #pragma unroll
    for (int jj = 0; jj < 5; ++jj) {
      int m = m0 + tx + 32*jj;
      if (m < MDIM) g_Tp[p*MDIM + m] = acc[i][jj] + T[p*MDIM + m];
    }
  }
}

// ---------------- LBS blend + verts + E_D ----------------
__global__ void lbs_kernel(const float* __restrict__ V, float* __restrict__ verts) {
  __shared__ float Gs[288];
  __shared__ float sb[8];
  int p = blockIdx.y;
  int n = blockIdx.x*blockDim.x + threadIdx.x;
  for (int i = threadIdx.x; i < 288; i += blockDim.x) Gs[i] = g_Gp[p*288 + i];
  __syncthreads();
  float ed = 0.f;
  if (n < NVERT) {
    float M[12];
    #pragma unroll
    for (int i = 0; i < 12; ++i) M[i] = 0.f;
    #pragma unroll
    for (int k = 0; k < NJ; ++k) {
      float w = g_WcT[k*NVERT + n];
      #pragma unroll
      for (int i = 0; i < 12; ++i) M[i] += w*Gs[k*12 + i];
    }
    int base = p*MDIM + 3*n;
    float t0 = g_Tp[base], t1 = g_Tp[base+1], t2 = g_Tp[base+2];
    float vx = M[0]*t0 + M[1]*t1 + M[2]*t2  + M[3];
    float vy = M[4]*t0 + M[5]*t1 + M[6]*t2  + M[7];
    float vz = M[8]*t0 + M[9]*t1 + M[10]*t2 + M[11];
    verts[base]   = vx;
    verts[base+1] = vy;
    verts[base+2] = vz;
    float dx = V[base]-vx, dy = V[base+1]-vy, dz = V[base+2]-vz;
    ed = dx*dx + dy*dy + dz*dz;
  }
  for (int o = 16; o > 0; o >>= 1) ed += __shfl_down_sync(0xffffffffu, ed, o);
  int lane = threadIdx.x & 31, wid = threadIdx.x >> 5;
  if (lane == 0) sb[wid] = ed;
  __syncthreads();
  if (wid == 0) {
    ed = (lane < 8) ? sb[lane] : 0.f;
    for (int o = 4; o > 0; o >>= 1) ed += __shfl_down_sync(0xffffffffu, ed, o);
    if (lane == 0) atomicAdd(&g_acc[0], ed);
  }
}

// ---------------- E assembly ----------------
__global__ void finalize_kernel(const int* __restrict__ epoch_ptr, int has_epoch,
                                float* __restrict__ outE) {
  float e = has_epoch ? (float)epoch_ptr[0] : 1.f;
  float g_wi = 0.1f  *expf(-0.1f  *e);
  float g_w  = 0.002f*expf(-0.008f*e);
  float g_a  = 0.001f*expf(-0.008f*e);
  float g_k  = 0.1f  *expf(-0.008f*e);
  float ek = 0.f;
  for (int j = 0; j < 23; ++j) ek += sqrtf(g_acc[4+j]);
  outE[0] = g_acc[0] + g_wi*g_acc[1] + g_w*g_acc[2] + g_a*g_acc[3] + g_k*ek;
}

extern "C" void kernel_launch(void* const* d_in, const int* in_sizes, int n_in,
                              void* d_out, int out_size) {
  const float* V  = (const float*)d_in[0];
  const float* T  = (const float*)d_in[1];
  const float* J  = (const float*)d_in[2];
  const float* th = (const float*)d_in[3];
  const float* Wp = (const float*)d_in[4];
  const float* Wi = (const float*)d_in[5];
  const float* A  = (const float*)d_in[6];
  const float* K  = (const float*)d_in[7];
  const float* b2 = (const float*)d_in[8];
  const int*   ep = (n_in > 9) ? (const int*)d_in[9] : nullptr;

  float* out = (float*)d_out;
  int off = out_size - NP*MDIM;      // extra elements for scalar E (expected 1)
  if (off < 0) off = 0;
  float* verts = out + off;          // E-first layout: verts after the scalar

  init_kernel<<<1, 32>>>();
  pose_kernel<<<4, 64>>>(th, J, b2);
  w_kernel<<<(NVERT + 255)/256, 256>>>(Wp, Wi, A);
  kprime_kernel<<<RDIM, 256>>>(A, K);
  gemm_kernel<<<dim3((MDIM + GBN - 1)/GBN, NP/GBM), 256>>>(T);
  lbs_kernel<<<dim3((NVERT + 255)/256, NP), 256>>>(V, verts);
  if (off > 0) finalize_kernel<<<1, 1>>>(ep, ep != nullptr ? 1 : 0, out);
}

// round 3
// speedup vs baseline: 1.2222x; 1.2222x over previous
#include <cuda_runtime.h>

#define NP    200
#define NVERT 6890
#define NJ    24
#define MDIM  20670   // NVERT*3
#define GBM   40
#define GBN   192     // 96 f32x2 pairs
#define PC    8       // poses per LBS block

__constant__ int c_PARENT[NJ] = {0,0,0,0,1,2,3,4,5,6,7,8,9,9,9,12,13,14,16,17,18,19,20,21};
__constant__ int c_LEN[NJ]    = {4,3,3,3,3,3,3,3,3,2,2,2,4,3,3,2,3,3,3,3,3,3,2,2};
__constant__ int c_LIM[23]    = {17,13,13,13,13,13,13,13,13,9,9,9,17,13,13,9,13,13,13,13,13,13,9};
__constant__ int c_NBR[NJ][4] = {
  {0,1,2,3},{0,1,4,0},{0,2,5,0},{0,3,6,0},{1,4,7,0},{2,5,8,0},{3,6,9,0},{4,7,10,0},
  {5,8,11,0},{6,9,0,0},{7,10,0,0},{8,11,0,0},{12,13,14,15},{12,13,16,0},{12,14,17,0},{12,15,0,0},
  {13,16,18,0},{14,17,19,0},{16,18,20,0},{17,19,21,0},{18,20,22,0},{19,21,23,0},{20,22,0,0},{21,23,0,0}};

// Scratch (static device globals; no runtime allocation)
__device__ float g_QMT[23*17*NP];   // qm transposed: [r][p]
__device__ float g_Gp [NP*NJ*12];   // per-pose 3x4 world transforms
__device__ float g_Wc [NVERT*NJ];   // normalized weights, row-major [n][k]
__device__ float g_Tp [NP*MDIM];    // T_p = QM @ (A.K) + T
__device__ float g_acc[32];         // 0:E_D 1:E_Wi 2:E_W 3:E_A 4..26:E_K[j] (ssq)

// ---- packed f32x2 helpers (sm_100+) ----
__device__ __forceinline__ unsigned long long pk2(float lo, float hi) {
  unsigned long long d;
  asm("mov.b64 %0, {%1,%2};" : "=l"(d) : "f"(lo), "f"(hi));
  return d;
}
__device__ __forceinline__ void upk2(unsigned long long v, float& lo, float& hi) {
  asm("mov.b64 {%0,%1}, %2;" : "=f"(lo), "=f"(hi) : "l"(v));
}
__device__ __forceinline__ void fma2(unsigned long long& d, unsigned long long a,
                                     unsigned long long b) {
  asm("fma.rn.f32x2 %0, %1, %2, %0;" : "+l"(d) : "l"(a), "l"(b));
}

__global__ void init_kernel() {
  if (threadIdx.x < 32) g_acc[threadIdx.x] = 0.f;
}

// ---------------- per-pose: quats, qm rows, kinematic chain ----------------
__global__ void pose_kernel(const float* __restrict__ theta,
                            const float* __restrict__ Jin,
                            const float* __restrict__ beta2) {
  int p = blockIdx.x*blockDim.x + threadIdx.x;
  if (p >= NP) return;
  const float* th = theta + p*72;
  const float* Jp = Jin + p*72;

  float q[NJ][4];
  float Rl[NJ][9];
  float tl[NJ][3];
  for (int k = 0; k < NJ; ++k) {
    float x = th[3*k], y = th[3*k+1], z = th[3*k+2];
    float s2 = x*x + y*y + z*z;
    float aq = sqrtf(fmaxf(s2, 1e-16f));
    float sh = sinf(0.5f*aq);
    float iq = 1.f/aq;
    q[k][0] = x*iq*sh; q[k][1] = y*iq*sh; q[k][2] = z*iq*sh;
    q[k][3] = cosf(0.5f*aq) - 1.f;
    float a = fmaxf(sqrtf(s2), 1e-8f);
    float ia = 1.f/a;
    float nx = x*ia, ny = y*ia, nz = z*ia;
    float c = cosf(a), s = sinf(a), t1 = 1.f - c;
    Rl[k][0] = c + t1*nx*nx;    Rl[k][1] = t1*nx*ny - s*nz; Rl[k][2] = t1*nx*nz + s*ny;
    Rl[k][3] = t1*nx*ny + s*nz; Rl[k][4] = c + t1*ny*ny;    Rl[k][5] = t1*ny*nz - s*nx;
    Rl[k][6] = t1*nx*nz - s*ny; Rl[k][7] = t1*ny*nz + s*nx; Rl[k][8] = c + t1*nz*nz;
    if (k == 0) { tl[k][0]=Jp[0]; tl[k][1]=Jp[1]; tl[k][2]=Jp[2]; }
    else {
      int par = c_PARENT[k];
      tl[k][0] = Jp[3*k]   - Jp[3*par];
      tl[k][1] = Jp[3*k+1] - Jp[3*par+1];
      tl[k][2] = Jp[3*k+2] - Jp[3*par+2];
    }
  }
  float Rw[NJ][9], tw[NJ][3];
  for (int i = 0; i < 9; ++i) Rw[0][i] = Rl[0][i];
  for (int i = 0; i < 3; ++i) tw[0][i] = tl[0][i];
  for (int k = 1; k < NJ; ++k) {
    int par = c_PARENT[k];
    for (int i = 0; i < 3; ++i) {
      for (int j = 0; j < 3; ++j) {
        Rw[k][i*3+j] = Rw[par][i*3+0]*Rl[k][0+j] + Rw[par][i*3+1]*Rl[k][3+j] + Rw[par][i*3+2]*Rl[k][6+j];
      }
      tw[k][i] = Rw[par][i*3+0]*tl[k][0] + Rw[par][i*3+1]*tl[k][1] + Rw[par][i*3+2]*tl[k][2] + tw[par][i];
    }
  }
  for (int k = 0; k < NJ; ++k) {
    float jx = Jp[3*k], jy = Jp[3*k+1], jz = Jp[3*k+2];
    for (int i = 0; i < 3; ++i) {
      float off = Rw[k][i*3]*jx + Rw[k][i*3+1]*jy + Rw[k][i*3+2]*jz;
      g_Gp[p*288 + k*12 + i*4 + 0] = Rw[k][i*3+0];
      g_Gp[p*288 + k*12 + i*4 + 1] = Rw[k][i*3+1];
      g_Gp[p*288 + k*12 + i*4 + 2] = Rw[k][i*3+2];
      g_Gp[p*288 + k*12 + i*4 + 3] = tw[k][i] - off;
    }
  }
  float b2 = beta2[0];
  for (int j = 0; j < 23; ++j) {
    int jj = j + 1;
    int limit = 4*c_LEN[j] + 1;
    int bpos  = 4*c_LEN[jj];
    for (int l = 0; l < 17; ++l) {
      float v = 0.f;
      if (l < 16) {
        int g = l >> 2, cc = l & 3;
        if (g < c_LEN[jj]) v = q[c_NBR[jj][g]][cc];
      }
      if (l == bpos) v += b2;
      if (l >= limit) v = 0.f;
      g_QMT[(j*17 + l)*NP + p] = v;
    }
  }
}

// ---------------- weights: W_change, E_Wi, E_W, E_A ----------------
__global__ void w_kernel(const float* __restrict__ Wp, const float* __restrict__ Wi,
                         const float* __restrict__ A) {
  __shared__ float sb0[8], sb1[8], sb2[8];
  int n = blockIdx.x*blockDim.x + threadIdx.x;
  float ewi = 0.f, ew = 0.f, ea = 0.f;
  if (n < NVERT) {
    float w[NJ]; float s = 0.f;
    #pragma unroll
    for (int k = 0; k < NJ; ++k) { w[k] = fmaxf(Wp[n*NJ+k], 0.f); s += w[k]; }
    float inv = 1.f/(s + 1e-8f);
    #pragma unroll
    for (int k = 0; k < NJ; ++k) {
      float wc = w[k]*inv;
      g_Wc[n*NJ + k] = wc;
      float d = wc - Wi[n*NJ+k];
      ewi += d*d;
      ew  += fabsf(wc);
    }
    for (int j = 0; j < 23; ++j) ea += fabsf(A[j*NVERT + n]);
  }
  for (int o = 16; o > 0; o >>= 1) {
    ewi += __shfl_down_sync(0xffffffffu, ewi, o);
    ew  += __shfl_down_sync(0xffffffffu, ew,  o);
    ea  += __shfl_down_sync(0xffffffffu, ea,  o);
  }
  int lane = threadIdx.x & 31, wid = threadIdx.x >> 5;
  if (lane == 0) { sb0[wid]=ewi; sb1[wid]=ew; sb2[wid]=ea; }
  __syncthreads();
  if (wid == 0) {
    ewi = (lane < 8) ? sb0[lane] : 0.f;
    ew  = (lane < 8) ? sb1[lane] : 0.f;
    ea  = (lane < 8) ? sb2[lane] : 0.f;
    for (int o = 4; o > 0; o >>= 1) {
      ewi += __shfl_down_sync(0xffffffffu, ewi, o);
      ew  += __shfl_down_sync(0xffffffffu, ew,  o);
      ea  += __shfl_down_sync(0xffffffffu, ea,  o);
    }
    if (lane == 0) {
      atomicAdd(&g_acc[1], ewi);
      atomicAdd(&g_acc[2], ew);
      atomicAdd(&g_acc[3], ea);
    }
  }
}

// ---------------- fused GEMM: T_p = QM @ (relu(A).K) + T, with E_K ----------------
// Per-thread micro-tile: 5 p-rows x 3 f32x2 column-pairs (6 columns).
// Column map: m = m0 + 2*tx + 64*jj (pairs contiguous -> LDS.64).
__global__ void __launch_bounds__(256) gemm_kernel(const float* __restrict__ K,
                                                   const float* __restrict__ A,
                                                   const float* __restrict__ T) {
  __shared__ __align__(16) unsigned long long As2[17][GBM];  // qm duplicated pairs
  __shared__ __align__(16) float Bs[17][GBN];
  __shared__ __align__(16) float Aws[GBN];
  int m0 = blockIdx.x*GBN;
  int p0 = blockIdx.y*GBM;
  int tid = threadIdx.x;
  int tx = tid & 31, ty = tid >> 5;   // 32 x 8
  bool do_ek = (blockIdx.y == 0);

  unsigned long long acc[5][3];
  #pragma unroll
  for (int i = 0; i < 5; ++i)
    #pragma unroll
    for (int jj = 0; jj < 3; ++jj) acc[i][jj] = 0ull;

  for (int jb = 0; jb < 23; ++jb) {
    int lim = c_LIM[jb];
    // fill A (qm) tile, duplicated into both f32x2 halves
    for (int i = tid; i < lim*GBM; i += 256) {
      int l = i / GBM, pp = i - l*GBM;
      float v = g_QMT[(jb*17 + l)*NP + p0 + pp];
      As2[l][pp] = pk2(v, v);
    }
    // fill B (K) tile + E_K partial
    float ss = 0.f;
    for (int i = tid; i < lim*GBN; i += 256) {
      int l = i / GBN, mm = i - l*GBN;
      int m = m0 + mm;
      float kv = (m < MDIM) ? K[(size_t)(jb*17 + l)*MDIM + m] : 0.f;
      Bs[l][mm] = kv;
      ss += kv*kv;
    }
    // fill relu(A) row for this j
    if (tid < GBN) {
      int m = m0 + tid;
      Aws[tid] = (m < MDIM) ? fmaxf(A[jb*NVERT + m/3], 0.f) : 0.f;
    }
    if (do_ek) {
      for (int o = 16; o > 0; o >>= 1) ss += __shfl_down_sync(0xffffffffu, ss, o);
      if (tx == 0) atomicAdd(&g_acc[4 + jb], ss);
    }
    __syncthreads();

    unsigned long long part[5][3];
    #pragma unroll
    for (int i = 0; i < 5; ++i)
      #pragma unroll
      for (int jj = 0; jj < 3; ++jj) part[i][jj] = 0ull;

    const unsigned long long* Bsu = reinterpret_cast<const unsigned long long*>(&Bs[0][0]);
    for (int l = 0; l < lim; ++l) {
      unsigned long long a2[5], b2v[3];
      #pragma unroll
      for (int i = 0; i < 5; ++i) a2[i] = As2[l][ty + 8*i];
      #pragma unroll
      for (int jj = 0; jj < 3; ++jj) b2v[jj] = Bsu[l*(GBN/2) + tx + 32*jj];
      #pragma unroll
      for (int i = 0; i < 5; ++i)
        #pragma unroll
        for (int jj = 0; jj < 3; ++jj) fma2(part[i][jj], a2[i], b2v[jj]);
    }
    // scale by relu(A[j, n(m)]) and accumulate
    const unsigned long long* Awsu = reinterpret_cast<const unsigned long long*>(&Aws[0]);
    unsigned long long awp[3];
    #pragma unroll
    for (int jj = 0; jj < 3; ++jj) awp[jj] = Awsu[tx + 32*jj];
    #pragma unroll
    for (int i = 0; i < 5; ++i)
      #pragma unroll
      for (int jj = 0; jj < 3; ++jj) fma2(acc[i][jj], awp[jj], part[i][jj]);
    __syncthreads();
  }
  // epilogue: += T, store
  #pragma unroll
  for (int i = 0; i < 5; ++i) {
    int p = p0 + ty + 8*i;
    #pragma unroll
    for (int jj = 0; jj < 3; ++jj) {
      int m = m0 + 2*tx + 64*jj;
      if (m < MDIM) {  // MDIM even, m even -> pair fully in range
        float lo, hi;
        upk2(acc[i][jj], lo, hi);
        float2 t = *reinterpret_cast<const float2*>(&T[(size_t)p*MDIM + m]);
        float2 r; r.x = lo + t.x; r.y = hi + t.y;
        *reinterpret_cast<float2*>(&g_Tp[(size_t)p*MDIM + m]) = r;
      }
    }
  }
}

// ---------------- LBS blend + verts + E_D ----------------
// thread = vertex; loop over PC poses; weights in regs; G in smem as float4.
__global__ void __launch_bounds__(128) lbs_kernel(const float* __restrict__ V,
                                                  float* __restrict__ verts) {
  __shared__ __align__(16) float Gs[PC*288];
  __shared__ float sb[4];
  int tid = threadIdx.x;
  int p0 = blockIdx.y*PC;
  for (int i = tid; i < PC*288; i += 128) Gs[i] = g_Gp[p0*288 + i];
  __syncthreads();
  int n = blockIdx.x*128 + tid;
  float w[NJ];
  bool ok = (n < NVERT);
  if (ok) {
    const float4* wp = reinterpret_cast<const float4*>(&g_Wc[n*NJ]);
    #pragma unroll
    for (int k4 = 0; k4 < 6; ++k4) {
      float4 v = wp[k4];
      w[4*k4] = v.x; w[4*k4+1] = v.y; w[4*k4+2] = v.z; w[4*k4+3] = v.w;
    }
  }
  float ed = 0.f;
  #pragma unroll
  for (int pp = 0; pp < PC; ++pp) {
    if (!ok) break;
    int p = p0 + pp;
    float4 M0 = make_float4(0.f,0.f,0.f,0.f);
    float4 M1 = M0, M2 = M0;
    const float4* Gp4 = reinterpret_cast<const float4*>(&Gs[pp*288]);
    #pragma unroll
    for (int k = 0; k < NJ; ++k) {
      float wk = w[k];
      float4 g0 = Gp4[k*3+0], g1 = Gp4[k*3+1], g2 = Gp4[k*3+2];
      M0.x += wk*g0.x; M0.y += wk*g0.y; M0.z += wk*g0.z; M0.w += wk*g0.w;
      M1.x += wk*g1.x; M1.y += wk*g1.y; M1.z += wk*g1.z; M1.w += wk*g1.w;
      M2.x += wk*g2.x; M2.y += wk*g2.y; M2.z += wk*g2.z; M2.w += wk*g2.w;
    }
    size_t base = (size_t)p*MDIM + 3*n;
    float t0 = g_Tp[base], t1 = g_Tp[base+1], t2 = g_Tp[base+2];
    float vx = M0.x*t0 + M0.y*t1 + M0.z*t2 + M0.w;
    float vy = M1.x*t0 + M1.y*t1 + M1.z*t2 + M1.w;
    float vz = M2.x*t0 + M2.y*t1 + M2.z*t2 + M2.w;
    verts[base]   = vx;
    verts[base+1] = vy;
    verts[base+2] = vz;
    float dx = V[base]-vx, dy = V[base+1]-vy, dz = V[base+2]-vz;
    ed += dx*dx + dy*dy + dz*dz;
  }
  for (int o = 16; o > 0; o >>= 1) ed += __shfl_down_sync(0xffffffffu, ed, o);
  int lane = tid & 31, wid = tid >> 5;
  if (lane == 0) sb[wid] = ed;
  __syncthreads();
  if (tid == 0) {
    atomicAdd(&g_acc[0], sb[0] + sb[1] + sb[2] + sb[3]);
  }
}

// ---------------- E assembly ----------------
__global__ void finalize_kernel(const int* __restrict__ epoch_ptr, int has_epoch,
                                float* __restrict__ outE) {
  float e = has_epoch ? (float)epoch_ptr[0] : 1.f;
  float g_wi = 0.1f  *expf(-0.1f  *e);
  float g_w  = 0.002f*expf(-0.008f*e);
  float g_a  = 0.001f*expf(-0.008f*e);
  float g_k  = 0.1f  *expf(-0.008f*e);
  float ek = 0.f;
  for (int j = 0; j < 23; ++j) ek += sqrtf(g_acc[4+j]);
  outE[0] = g_acc[0] + g_wi*g_acc[1] + g_w*g_acc[2] + g_a*g_acc[3] + g_k*ek;
}

extern "C" void kernel_launch(void* const* d_in, const int* in_sizes, int n_in,
                              void* d_out, int out_size) {
  const float* V  = (const float*)d_in[0];
  const float* T  = (const float*)d_in[1];
  const float* J  = (const float*)d_in[2];
  const float* th = (const float*)d_in[3];
  const float* Wp = (const float*)d_in[4];
  const float* Wi = (const float*)d_in[5];
  const float* A  = (const float*)d_in[6];
  const float* K  = (const float*)d_in[7];
  const float* b2 = (const float*)d_in[8];
  const int*   ep = (n_in > 9) ? (const int*)d_in[9] : nullptr;

  float* out = (float*)d_out;
  int off = out_size - NP*MDIM;
  if (off < 0) off = 0;
  float* verts = out + off;

  init_kernel<<<1, 32>>>();
  pose_kernel<<<4, 64>>>(th, J, b2);
  w_kernel<<<(NVERT + 255)/256, 256>>>(Wp, Wi, A);
  gemm_kernel<<<dim3((MDIM + GBN - 1)/GBN, NP/GBM), 256>>>(K, A, T);
  lbs_kernel<<<dim3((NVERT + 127)/128, NP/PC), 128>>>(V, verts);
  if (off > 0) finalize_kernel<<<1, 1>>>(ep, ep != nullptr ? 1 : 0, out);
}